// round 3
// baseline (speedup 1.0000x reference)
#include <cuda_runtime.h>
#include <cuda_bf16.h>
#include <math.h>

// ---------------------------------------------------------------------------
// 2-layer GCN, N=1M, E=4M, 4 -> 16 -> 2, log_softmax.
// Linearity: layer-1 scatter moves xs = x*dinv; W1 applied post-aggregation.
// Self-loops folded by initializing accumulators to the node's own message.
// 4 edges/thread in scatters for MLP; packed int2 edge scratch.
// ---------------------------------------------------------------------------

#define NMAX 1048576
#define EMAX 4194304

__device__ int2  g_edges[EMAX];      // packed (src, dst)
__device__ int   g_deg  [NMAX];
__device__ float g_dinv [NMAX];
__device__ float g_xs   [NMAX * 4];  // x * dinv
__device__ float g_a1   [NMAX * 4];  // layer-1 acc, init = xs (self loop)
__device__ float g_h2   [NMAX * 2];  // (h@W2)*dinv
__device__ float g_a2   [NMAX * 2];  // layer-2 acc, init = h2 (self loop)
__device__ int   g_ei64;

#define RED4(idx, v) \
    asm volatile("red.global.add.v4.f32 [%0], {%1,%2,%3,%4};" \
                 :: "l"(&((float4*)g_a1)[idx]), "f"((v).x), "f"((v).y), "f"((v).z), "f"((v).w) : "memory")
#define RED2(idx, v) \
    asm volatile("red.global.add.v2.f32 [%0], {%1,%2};" \
                 :: "l"(&((float2*)g_a2)[idx]), "f"((v).x), "f"((v).y) : "memory")

// --- dtype detection: int64 indices < 2^20 have all-zero high words --------
__global__ void k_detect(const unsigned* ei) {
    if (threadIdx.x == 0 && blockIdx.x == 0) {
        int nz = 0;
        for (int e = 0; e < 256; e++) nz += (ei[2 * e + 1] != 0u);
        g_ei64 = (nz == 0) ? 1 : 0;
    }
}

__global__ void k_deg_init(int N4) {  // N4 = ceil(N/4)
    int i = blockIdx.x * blockDim.x + threadIdx.x;
    if (i < N4) ((int4*)g_deg)[i] = make_int4(1, 1, 1, 1);  // self loop
}

// --- convert edges to packed int2 + fused degree count (2 edges/thread) ---
__global__ void k_conv(const void* ei, int E) {
    int t = blockIdx.x * blockDim.x + threadIdx.x;
    int e0 = t * 2;
    if (e0 >= E) return;
    int s0, d0, s1, d1;
    bool two = (e0 + 1 < E);
    if (g_ei64) {
        const long long* p = (const long long*)ei;
        if (two) {
            longlong2 ss = __ldg((const longlong2*)(p + e0));
            longlong2 dd = __ldg((const longlong2*)(p + E + e0));
            s0 = (int)ss.x; s1 = (int)ss.y; d0 = (int)dd.x; d1 = (int)dd.y;
        } else {
            s0 = (int)__ldg(p + e0); d0 = (int)__ldg(p + E + e0); s1 = d1 = 0;
        }
    } else {
        const int* p = (const int*)ei;
        if (two) {
            int2 ss = __ldg((const int2*)(p + e0));
            int2 dd = __ldg((const int2*)(p + E + e0));
            s0 = ss.x; s1 = ss.y; d0 = dd.x; d1 = dd.y;
        } else {
            s0 = __ldg(p + e0); d0 = __ldg(p + E + e0); s1 = d1 = 0;
        }
    }
    if (two) {
        ((int4*)g_edges)[t] = make_int4(s0, d0, s1, d1);
        atomicAdd(&g_deg[d0], 1);
        atomicAdd(&g_deg[d1], 1);
    } else {
        g_edges[e0] = make_int2(s0, d0);
        atomicAdd(&g_deg[d0], 1);
    }
}

// --- node pass 1: dinv, xs = x*dinv, a1 = xs (2 nodes/thread) -------------
__global__ void k_l1(const float* __restrict__ x, int N) {
    int t = blockIdx.x * blockDim.x + threadIdx.x;
    int i0 = t * 2;
    if (i0 >= N) return;
#pragma unroll
    for (int j = 0; j < 2; j++) {
        int i = i0 + j;
        if (i >= N) break;
        float4 xv = __ldg(&((const float4*)x)[i]);
        float di = rsqrtf((float)g_deg[i]);
        g_dinv[i] = di;
        float4 v = make_float4(xv.x * di, xv.y * di, xv.z * di, xv.w * di);
        ((float4*)g_xs)[i] = v;
        ((float4*)g_a1)[i] = v;  // self-loop contribution
    }
}

// --- layer-1 edge scatter: a1[dst] += xs[src] (4 edges/thread) ------------
__global__ void k_sc1(int E) {
    int t = blockIdx.x * blockDim.x + threadIdx.x;
    int e0 = t * 4;
    if (e0 >= E) return;
    if (e0 + 3 < E) {
        int4 ea = ((const int4*)g_edges)[t * 2];
        int4 eb = ((const int4*)g_edges)[t * 2 + 1];
        float4 v0 = __ldg(&((const float4*)g_xs)[ea.x]);
        float4 v1 = __ldg(&((const float4*)g_xs)[ea.z]);
        float4 v2 = __ldg(&((const float4*)g_xs)[eb.x]);
        float4 v3 = __ldg(&((const float4*)g_xs)[eb.z]);
        RED4(ea.y, v0); RED4(ea.w, v1); RED4(eb.y, v2); RED4(eb.w, v3);
    } else {
        for (int e = e0; e < E; e++) {
            int2 sd = g_edges[e];
            float4 v = __ldg(&((const float4*)g_xs)[sd.x]);
            RED4(sd.y, v);
        }
    }
}

// --- node pass 2: h = relu(dinv*(a1@W1)+b1); h2 = (h@W2)*dinv; a2 = h2 ----
__global__ void k_l2(const float* __restrict__ W1, const float* __restrict__ b1,
                     const float* __restrict__ W2, int N) {
    int i = blockIdx.x * blockDim.x + threadIdx.x;
    if (i >= N) return;
    float di = g_dinv[i];
    float4 av = ((const float4*)g_a1)[i];   // includes self loop
    float o0 = 0.f, o1 = 0.f;
#pragma unroll
    for (int k = 0; k < 16; k++) {
        float h = di * (av.x * __ldg(W1 + k)      + av.y * __ldg(W1 + 16 + k) +
                        av.z * __ldg(W1 + 32 + k) + av.w * __ldg(W1 + 48 + k)) + __ldg(b1 + k);
        h = fmaxf(h, 0.f);
        o0 += h * __ldg(W2 + 2 * k);
        o1 += h * __ldg(W2 + 2 * k + 1);
    }
    float2 v = make_float2(o0 * di, o1 * di);
    ((float2*)g_h2)[i] = v;
    ((float2*)g_a2)[i] = v;  // self-loop contribution
}

// --- layer-2 edge scatter: a2[dst] += h2[src] (4 edges/thread) ------------
__global__ void k_sc2(int E) {
    int t = blockIdx.x * blockDim.x + threadIdx.x;
    int e0 = t * 4;
    if (e0 >= E) return;
    if (e0 + 3 < E) {
        int4 ea = ((const int4*)g_edges)[t * 2];
        int4 eb = ((const int4*)g_edges)[t * 2 + 1];
        float2 v0 = __ldg(&((const float2*)g_h2)[ea.x]);
        float2 v1 = __ldg(&((const float2*)g_h2)[ea.z]);
        float2 v2 = __ldg(&((const float2*)g_h2)[eb.x]);
        float2 v3 = __ldg(&((const float2*)g_h2)[eb.z]);
        RED2(ea.y, v0); RED2(ea.w, v1); RED2(eb.y, v2); RED2(eb.w, v3);
    } else {
        for (int e = e0; e < E; e++) {
            int2 sd = g_edges[e];
            float2 v = __ldg(&((const float2*)g_h2)[sd.x]);
            RED2(sd.y, v);
        }
    }
}

// --- output: o = dinv*a2 + b2; log_softmax over 2 classes -----------------
__global__ void k_out(const float* __restrict__ b2, float* __restrict__ out, int N) {
    int i = blockIdx.x * blockDim.x + threadIdx.x;
    if (i >= N) return;
    float di = g_dinv[i];
    float2 a = ((const float2*)g_a2)[i];    // includes self loop
    float o0 = di * a.x + __ldg(b2);
    float o1 = di * a.y + __ldg(b2 + 1);
    float m = fmaxf(o0, o1);
    float ls = m + logf(expf(o0 - m) + expf(o1 - m));
    ((float2*)out)[i] = make_float2(o0 - ls, o1 - ls);
}

extern "C" void kernel_launch(void* const* d_in, const int* in_sizes, int n_in,
                              void* d_out, int out_size) {
    const float* x  = (const float*)d_in[0];
    const void*  ei = d_in[1];
    int wi = 2;
    if (n_in >= 7 && in_sizes[2] < 16) wi = 3;  // skip num_nodes scalar
    const float* W1 = (const float*)d_in[wi];
    const float* b1 = (const float*)d_in[wi + 1];
    const float* W2 = (const float*)d_in[wi + 2];
    const float* b2 = (const float*)d_in[wi + 3];

    int N = in_sizes[0] / 4;
    int E = in_sizes[1] / 2;

    const int T = 256;
    int gN  = (N + T - 1) / T;
    int N4  = (N + 3) / 4;
    int gN4 = (N4 + T - 1) / T;
    int gN2 = ((N + 1) / 2 + T - 1) / T;
    int gE2 = ((E + 1) / 2 + T - 1) / T;
    int gE4 = ((E + 3) / 4 + T - 1) / T;

    k_detect<<<1, 32>>>((const unsigned*)ei);
    k_deg_init<<<gN4, T>>>(N4);
    k_conv<<<gE2, T>>>(ei, E);
    k_l1<<<gN2, T>>>(x, N);
    k_sc1<<<gE4, T>>>(E);
    k_l2<<<gN, T>>>(W1, b1, W2, N);
    k_sc2<<<gE4, T>>>(E);
    k_out<<<gN, T>>>(b2, (float*)d_out, N);
}

// round 4
// speedup vs baseline: 1.1245x; 1.1245x over previous
#include <cuda_runtime.h>
#include <cuda_bf16.h>
#include <math.h>

// ---------------------------------------------------------------------------
// 2-layer GCN, N=1M, E=4M, 4 -> 16 -> 2, log_softmax.
// Linearity: layer-1 scatter moves xs = x*dinv; W1 applied post-aggregation.
// Self-loops folded by initializing accumulators to the node's own message.
// deg zeroed via memset; dinv = rsqrt(deg+1).
// ---------------------------------------------------------------------------

#define NMAX 1048576
#define EMAX 4194304

__device__ int2  g_edges[EMAX];      // packed (src, dst)
__device__ int   g_deg  [NMAX];
__device__ float g_dinv [NMAX];
__device__ float g_xs   [NMAX * 4];  // x * dinv
__device__ float g_a1   [NMAX * 4];  // layer-1 acc, init = xs (self loop)
__device__ float g_h2   [NMAX * 2];  // (h@W2)*dinv
__device__ float g_a2   [NMAX * 2];  // layer-2 acc, init = h2 (self loop)
__device__ int   g_ei64;

#define RED4(idx, v) \
    asm volatile("red.global.add.v4.f32 [%0], {%1,%2,%3,%4};" \
                 :: "l"(&((float4*)g_a1)[idx]), "f"((v).x), "f"((v).y), "f"((v).z), "f"((v).w) : "memory")
#define RED2(idx, v) \
    asm volatile("red.global.add.v2.f32 [%0], {%1,%2};" \
                 :: "l"(&((float2*)g_a2)[idx]), "f"((v).x), "f"((v).y) : "memory")
#define REDI(p) \
    asm volatile("red.global.add.u32 [%0], %1;" :: "l"(p), "r"(1) : "memory")

// --- dtype detection: int64 indices < 2^20 have all-zero high words --------
__global__ void k_detect(const unsigned* ei) {
    unsigned hi = ei[2 * threadIdx.x + 1];   // 32 samples
    unsigned any = __ballot_sync(0xffffffffu, hi != 0u);
    if (threadIdx.x == 0) g_ei64 = (any == 0u) ? 1 : 0;
}

// --- convert edges to packed int2 + fused degree count (2 edges/thread) ---
__global__ void k_conv(const void* ei, int E) {
    int t = blockIdx.x * blockDim.x + threadIdx.x;
    int e0 = t * 2;
    if (e0 >= E) return;
    int s0, d0, s1, d1;
    bool two = (e0 + 1 < E);
    if (g_ei64) {
        const long long* p = (const long long*)ei;
        if (two) {
            longlong2 ss = __ldg((const longlong2*)(p + e0));
            longlong2 dd = __ldg((const longlong2*)(p + E + e0));
            s0 = (int)ss.x; s1 = (int)ss.y; d0 = (int)dd.x; d1 = (int)dd.y;
        } else {
            s0 = (int)__ldg(p + e0); d0 = (int)__ldg(p + E + e0); s1 = d1 = 0;
        }
    } else {
        const int* p = (const int*)ei;
        if (two) {
            int2 ss = __ldg((const int2*)(p + e0));
            int2 dd = __ldg((const int2*)(p + E + e0));
            s0 = ss.x; s1 = ss.y; d0 = dd.x; d1 = dd.y;
        } else {
            s0 = __ldg(p + e0); d0 = __ldg(p + E + e0); s1 = d1 = 0;
        }
    }
    if (two) {
        ((int4*)g_edges)[t] = make_int4(s0, d0, s1, d1);
        REDI(&g_deg[d0]);
        REDI(&g_deg[d1]);
    } else {
        g_edges[e0] = make_int2(s0, d0);
        REDI(&g_deg[d0]);
    }
}

// --- node pass 1: dinv = rsqrt(deg+1), xs = x*dinv, a1 = xs ---------------
__global__ void k_l1(const float* __restrict__ x, int N) {
    int i = blockIdx.x * blockDim.x + threadIdx.x;
    if (i >= N) return;
    float4 xv = __ldg(&((const float4*)x)[i]);
    float di = rsqrtf((float)(g_deg[i] + 1));   // +1 = self loop
    g_dinv[i] = di;
    float4 v = make_float4(xv.x * di, xv.y * di, xv.z * di, xv.w * di);
    ((float4*)g_xs)[i] = v;
    ((float4*)g_a1)[i] = v;  // self-loop contribution
}

// --- layer-1 edge scatter: a1[dst] += xs[src] (4 edges/thread) ------------
__global__ void k_sc1(int E) {
    int t = blockIdx.x * blockDim.x + threadIdx.x;
    int e0 = t * 4;
    if (e0 >= E) return;
    if (e0 + 3 < E) {
        int4 ea = ((const int4*)g_edges)[t * 2];
        int4 eb = ((const int4*)g_edges)[t * 2 + 1];
        float4 v0 = __ldg(&((const float4*)g_xs)[ea.x]);
        float4 v1 = __ldg(&((const float4*)g_xs)[ea.z]);
        float4 v2 = __ldg(&((const float4*)g_xs)[eb.x]);
        float4 v3 = __ldg(&((const float4*)g_xs)[eb.z]);
        RED4(ea.y, v0); RED4(ea.w, v1); RED4(eb.y, v2); RED4(eb.w, v3);
    } else {
        for (int e = e0; e < E; e++) {
            int2 sd = g_edges[e];
            float4 v = __ldg(&((const float4*)g_xs)[sd.x]);
            RED4(sd.y, v);
        }
    }
}

// --- node pass 2: h = relu(dinv*(a1@W1)+b1); h2 = (h@W2)*dinv; a2 = h2 ----
__global__ void k_l2(const float* __restrict__ W1, const float* __restrict__ b1,
                     const float* __restrict__ W2, int N) {
    __shared__ float sW1[64], sb1[16], sW2[32];
    int tid = threadIdx.x;
    if (tid < 64)              sW1[tid]      = W1[tid];
    else if (tid < 80)         sb1[tid - 64] = b1[tid - 64];
    else if (tid < 112)        sW2[tid - 80] = W2[tid - 80];
    __syncthreads();

    int i = blockIdx.x * blockDim.x + tid;
    if (i >= N) return;
    float di = g_dinv[i];
    float4 av = ((const float4*)g_a1)[i];   // includes self loop
    float o0 = 0.f, o1 = 0.f;
#pragma unroll
    for (int k = 0; k < 16; k++) {
        float h = di * (av.x * sW1[k]      + av.y * sW1[16 + k] +
                        av.z * sW1[32 + k] + av.w * sW1[48 + k]) + sb1[k];
        h = fmaxf(h, 0.f);
        o0 += h * sW2[2 * k];
        o1 += h * sW2[2 * k + 1];
    }
    float2 v = make_float2(o0 * di, o1 * di);
    ((float2*)g_h2)[i] = v;
    ((float2*)g_a2)[i] = v;  // self-loop contribution
}

// --- layer-2 edge scatter: a2[dst] += h2[src] (4 edges/thread) ------------
__global__ void k_sc2(int E) {
    int t = blockIdx.x * blockDim.x + threadIdx.x;
    int e0 = t * 4;
    if (e0 >= E) return;
    if (e0 + 3 < E) {
        int4 ea = ((const int4*)g_edges)[t * 2];
        int4 eb = ((const int4*)g_edges)[t * 2 + 1];
        float2 v0 = __ldg(&((const float2*)g_h2)[ea.x]);
        float2 v1 = __ldg(&((const float2*)g_h2)[ea.z]);
        float2 v2 = __ldg(&((const float2*)g_h2)[eb.x]);
        float2 v3 = __ldg(&((const float2*)g_h2)[eb.z]);
        RED2(ea.y, v0); RED2(ea.w, v1); RED2(eb.y, v2); RED2(eb.w, v3);
    } else {
        for (int e = e0; e < E; e++) {
            int2 sd = g_edges[e];
            float2 v = __ldg(&((const float2*)g_h2)[sd.x]);
            RED2(sd.y, v);
        }
    }
}

// --- output: o = dinv*a2 + b2; log_softmax over 2 classes -----------------
__global__ void k_out(const float* __restrict__ b2, float* __restrict__ out, int N) {
    int i = blockIdx.x * blockDim.x + threadIdx.x;
    if (i >= N) return;
    float di = g_dinv[i];
    float2 a = ((const float2*)g_a2)[i];    // includes self loop
    float2 bb = __ldg((const float2*)b2);
    float o0 = di * a.x + bb.x;
    float o1 = di * a.y + bb.y;
    float m = fmaxf(o0, o1);
    float ls = m + __logf(__expf(o0 - m) + __expf(o1 - m));
    ((float2*)out)[i] = make_float2(o0 - ls, o1 - ls);
}

extern "C" void kernel_launch(void* const* d_in, const int* in_sizes, int n_in,
                              void* d_out, int out_size) {
    const float* x  = (const float*)d_in[0];
    const void*  ei = d_in[1];
    int wi = 2;
    if (n_in >= 7 && in_sizes[2] < 16) wi = 3;  // skip num_nodes scalar
    const float* W1 = (const float*)d_in[wi];
    const float* b1 = (const float*)d_in[wi + 1];
    const float* W2 = (const float*)d_in[wi + 2];
    const float* b2 = (const float*)d_in[wi + 3];

    int N = in_sizes[0] / 4;
    int E = in_sizes[1] / 2;

    const int T = 256;
    int gN  = (N + T - 1) / T;
    int gE2 = ((E + 1) / 2 + T - 1) / T;
    int gE4 = ((E + 3) / 4 + T - 1) / T;

    void* degp = nullptr;
    cudaGetSymbolAddress(&degp, g_deg);

    k_detect<<<1, 32>>>((const unsigned*)ei);
    cudaMemsetAsync(degp, 0, (size_t)N * sizeof(int));
    k_conv<<<gE2, T>>>(ei, E);
    k_l1<<<gN, T>>>(x, N);
    k_sc1<<<gE4, T>>>(E);
    k_l2<<<gN, T>>>(W1, b1, W2, N);
    k_sc2<<<gE4, T>>>(E);
    k_out<<<gN, T>>>(b2, (float*)d_out, N);
}